// round 6
// baseline (speedup 1.0000x reference)
#include <cuda_runtime.h>

#define BB   4
#define NNN  2048
#define CCC  256
#define HHH  8
#define DHH  32
#define WINW 16
#define SCALE 0.17677669529663687f   // 32^-0.5

typedef unsigned long long u64;

__device__ __forceinline__ u64 fma2(u64 a, u64 b, u64 c) {
    u64 d;
    asm("fma.rn.f32x2 %0, %1, %2, %3;" : "=l"(d) : "l"(a), "l"(b), "l"(c));
    return d;
}
__device__ __forceinline__ u64 pack2(float lo, float hi) {
    u64 d;
    asm("mov.b64 %0, {%1, %2};" : "=l"(d) : "f"(lo), "f"(hi));
    return d;
}
__device__ __forceinline__ float pairsum(u64 p) {
    float lo, hi;
    asm("mov.b64 {%0, %1}, %2;" : "=f"(lo), "=f"(hi) : "l"(p));
    return lo + hi;
}

// -------- scratch (device globals; no allocations allowed) --------
__device__ float g_qkv[3LL * BB * HHH * NNN * DHH];   // [3][B][H][N][32]  24 MB
__device__ float g_comb[(long long)BB * NNN * CCC];   // [B][N][C]          8 MB

// ============================================================
// Kernel 1: QKV GEMM.  X[8192,256] @ W[256,768] -> scatter to g_qkv
// ============================================================
__global__ __launch_bounds__(256) void qkv_gemm_kernel(const float* __restrict__ X,
                                                       const float* __restrict__ W) {
    __shared__ float Xs[16 * 68];
    __shared__ float Ws[16 * 64];
    const int t  = threadIdx.x;
    const int tx = t & 15, ty = t >> 4;
    const int m0 = blockIdx.y * 64;
    const int n0 = blockIdx.x * 64;

    float acc[4][4] = {};

    for (int k0 = 0; k0 < CCC; k0 += 16) {
        {
            int kk = t & 15, mloc = t >> 4;
            #pragma unroll
            for (int r = 0; r < 4; r++) {
                int m = mloc + r * 16;
                Xs[kk * 68 + m] = X[(long long)(m0 + m) * CCC + k0 + kk];
            }
        }
        {
            int nn = t & 63, kk = t >> 6;
            #pragma unroll
            for (int r = 0; r < 4; r++)
                Ws[(kk + r * 4) * 64 + nn] = W[(long long)(k0 + kk + r * 4) * 768 + n0 + nn];
        }
        __syncthreads();
        #pragma unroll
        for (int kk = 0; kk < 16; kk++) {
            float4 a = *(const float4*)(Xs + kk * 68 + ty * 4);
            float4 b = *(const float4*)(Ws + kk * 64 + tx * 4);
            acc[0][0] += a.x * b.x; acc[0][1] += a.x * b.y; acc[0][2] += a.x * b.z; acc[0][3] += a.x * b.w;
            acc[1][0] += a.y * b.x; acc[1][1] += a.y * b.y; acc[1][2] += a.y * b.z; acc[1][3] += a.y * b.w;
            acc[2][0] += a.z * b.x; acc[2][1] += a.z * b.y; acc[2][2] += a.z * b.z; acc[2][3] += a.z * b.w;
            acc[3][0] += a.w * b.x; acc[3][1] += a.w * b.y; acc[3][2] += a.w * b.z; acc[3][3] += a.w * b.w;
        }
        __syncthreads();
    }
    #pragma unroll
    for (int ii = 0; ii < 4; ii++) {
        int row = m0 + ty * 4 + ii;
        int b   = row >> 11;
        int n   = row & 2047;
        #pragma unroll
        for (int jj = 0; jj < 4; jj++) {
            int col = n0 + tx * 4 + jj;
            int t3  = col >> 8;
            int rem = col & 255;
            int h   = rem >> 5;
            int d   = rem & 31;
            g_qkv[((((long long)t3 * BB + b) * HHH + h) * NNN + n) * DHH + d] = acc[ii][jj];
        }
    }
}

// ============================================================
// Kernel 2: fused global attention per (b,h, 16-row block)
// f32x2 packed math in both GEMM phases.
// smem (floats):
//   S[16][2052]                 0      .. 32832
//   qs: 16 rows x stride 34     32832  (f32x2 pairs over d, scale folded)
//   rinv[16]                    33376
//   ks: 512 x 34                33392  (aliases vt 256x34, red 16x514)
// ============================================================
#define SS        2052
#define QS_OFF    (16 * SS)                 // 32832
#define RINV_OFF  (QS_OFF + 16 * 34)        // 33376
#define KS_OFF    (RINV_OFF + 16)           // 33392
#define ATTN_FLOATS (KS_OFF + 512 * 34)     // 50800
#define ATTN_SMEM (ATTN_FLOATS * 4)         // 203200 bytes

__global__ __launch_bounds__(256) void attn_global_kernel(float* __restrict__ out_w) {
    extern __shared__ float sm[];
    float* S    = sm;
    float* qs   = sm + QS_OFF;     // row stride 34 floats (17 f2-pairs over d)
    float* rinv = sm + RINV_OFF;
    float* ks   = sm + KS_OFF;     // ks[c][d], stride 34
    float* vt   = sm + KS_OFF;     // vt[c][d], stride 34 (alias)
    float* red  = sm + KS_OFF;     // red[kg][514]       (alias, after vt dead)

    const int t  = threadIdx.x;
    const int bh = blockIdx.y;
    const int i0 = blockIdx.x * 16;
    const float* Q = g_qkv + (long long)bh * NNN * DHH;
    const float* K = g_qkv + ((long long)BB * HHH + bh) * NNN * DHH;
    const float* V = g_qkv + ((long long)2 * BB * HHH + bh) * NNN * DHH;

    // ---- build packed q (real pairs over d, scale folded) ----
    {
        int r = t >> 4, d2 = t & 15;
        float2 qv = *(const float2*)(Q + (long long)(i0 + r) * DHH + 2 * d2);
        *(float2*)(qs + r * 34 + 2 * d2) = make_float2(qv.x * SCALE, qv.y * SCALE);
    }

    // ---------- Phase 1: S = q.K^T  (tiles of 512 cols, f32x2 over d) ----------
    {
        const int cg = t & 63, rg = t >> 6;
        for (int kj0 = 0; kj0 < NNN; kj0 += 512) {
            __syncthreads();
            // load K tile: ks[c][d], stride 34; float2 halves of each float4 (conflict-free STS.64)
            #pragma unroll
            for (int r = 0; r < 16; r++) {
                int idx = t + r * 256;
                int c = idx >> 3, f4 = idx & 7;
                float4 k4 = *(const float4*)(K + (long long)(kj0 + c) * DHH + f4 * 4);
                *(float2*)(ks + c * 34 + f4 * 4)     = make_float2(k4.x, k4.y);
                *(float2*)(ks + c * 34 + f4 * 4 + 2) = make_float2(k4.z, k4.w);
            }
            __syncthreads();

            u64 acc2[4][8] = {};
            #pragma unroll
            for (int d2 = 0; d2 < 16; d2++) {
                u64 q2[4];
                #pragma unroll
                for (int r = 0; r < 4; r++)
                    q2[r] = *(const u64*)(qs + (rg * 4 + r) * 34 + 2 * d2);   // broadcast
                u64 k2[8];
                #pragma unroll
                for (int cc = 0; cc < 8; cc++)
                    k2[cc] = *(const u64*)(ks + (cg + 64 * cc) * 34 + 2 * d2);
                #pragma unroll
                for (int r = 0; r < 4; r++)
                    #pragma unroll
                    for (int cc = 0; cc < 8; cc++)
                        acc2[r][cc] = fma2(q2[r], k2[cc], acc2[r][cc]);
            }
            #pragma unroll
            for (int r = 0; r < 4; r++)
                #pragma unroll
                for (int cc = 0; cc < 8; cc++)
                    S[(rg * 4 + r) * SS + kj0 + cg + 64 * cc] = pairsum(acc2[r][cc]);
        }
    }
    __syncthreads();

    // ---------- Phase 2: softmax stats; S := e (unnormalized) ----------
    {
        int row = t >> 4, lane = t & 15;
        float* Sr = S + row * SS;
        float m = -1e30f;
        #pragma unroll 8
        for (int i = 0; i < 32; i++) {
            float4 v = *(const float4*)(Sr + i * 64 + lane * 4);
            m = fmaxf(m, fmaxf(fmaxf(v.x, v.y), fmaxf(v.z, v.w)));
        }
        #pragma unroll
        for (int o = 8; o; o >>= 1) m = fmaxf(m, __shfl_xor_sync(0xffffffffu, m, o, 16));
        float ssum = 0.f;
        #pragma unroll 8
        for (int i = 0; i < 32; i++) {
            float4 v = *(float4*)(Sr + i * 64 + lane * 4);
            v.x = __expf(v.x - m); v.y = __expf(v.y - m);
            v.z = __expf(v.z - m); v.w = __expf(v.w - m);
            *(float4*)(Sr + i * 64 + lane * 4) = v;
            ssum += (v.x + v.y) + (v.z + v.w);
        }
        #pragma unroll
        for (int o = 8; o; o >>= 1) ssum += __shfl_xor_sync(0xffffffffu, ssum, o, 16);
        if (lane == 0) rinv[row] = 1.0f / ssum;
    }
    __syncthreads();

    // ---------- Phase 2b: write normalized weights to gmem (float4) ----------
    {
        float* wbase = out_w + (long long)bh * NNN * NNN + (long long)i0 * NNN;
        for (int i = 0; i < 16; i++) {
            float inv = rinv[i];
            #pragma unroll
            for (int r = 0; r < 2; r++) {
                int idx = t + r * 256;
                float4 v = *(const float4*)(S + i * SS + idx * 4);
                v.x *= inv; v.y *= inv; v.z *= inv; v.w *= inv;
                *(float4*)(wbase + (long long)i * NNN + idx * 4) = v;
            }
        }
    }

    // ---------- Phase 3: O = e.V  (16-way split-k, f32x2 over output dims) ----------
    {
        const int kg  = t & 15;          // split-k group
        const int d2g = (t >> 4) & 7;    // 4 output dims (2 f2-pairs)
        const int rg  = t >> 7;          // 8 rows
        u64 acc2[8][2] = {};

        for (int vj0 = 0; vj0 < NNN; vj0 += 256) {
            __syncthreads();
            #pragma unroll
            for (int r = 0; r < 8; r++) {
                int idx = t + r * 256;
                int c = idx >> 3, f4 = idx & 7;
                float4 v4 = *(const float4*)(V + (long long)(vj0 + c) * DHH + f4 * 4);
                *(float2*)(vt + c * 34 + f4 * 4)     = make_float2(v4.x, v4.y);
                *(float2*)(vt + c * 34 + f4 * 4 + 2) = make_float2(v4.z, v4.w);
            }
            __syncthreads();

            #pragma unroll 4
            for (int i = 0; i < 16; i++) {
                int kl = i * 16 + kg;
                u64 v2a = *(const u64*)(vt + kl * 34 + d2g * 4);
                u64 v2b = *(const u64*)(vt + kl * 34 + d2g * 4 + 2);
                #pragma unroll
                for (int rr = 0; rr < 8; rr++) {
                    float s = S[(rg * 8 + rr) * SS + vj0 + kl];
                    u64 sp = pack2(s, s);
                    acc2[rr][0] = fma2(sp, v2a, acc2[rr][0]);
                    acc2[rr][1] = fma2(sp, v2b, acc2[rr][1]);
                }
            }
        }
        __syncthreads();   // vt dead; region becomes red[]
        #pragma unroll
        for (int rr = 0; rr < 8; rr++) {
            *(u64*)(red + kg * 514 + (rg * 8 + rr) * 32 + d2g * 4)     = acc2[rr][0];
            *(u64*)(red + kg * 514 + (rg * 8 + rr) * 32 + d2g * 4 + 2) = acc2[rr][1];
        }
        __syncthreads();

        const int b = bh >> 3, h = bh & 7;
        #pragma unroll
        for (int s2 = 0; s2 < 2; s2++) {
            int out = t + s2 * 256;          // 512 outputs
            int row = out >> 5, d = out & 31;
            float sum = 0.f;
            #pragma unroll
            for (int k2 = 0; k2 < 16; k2++) sum += red[k2 * 514 + out];
            sum *= rinv[row];
            g_comb[((long long)b * NNN + i0 + row) * CCC + h * DHH + d] = sum;
        }
    }
}

// ============================================================
// Kernel 3: local window attention, accumulates into g_comb
// ============================================================
__global__ __launch_bounds__(128) void local_attn_kernel() {
    __shared__ float ql[16 * 33], kl[16 * 33], vl[16 * 33], sl[16 * 17];
    const int t  = threadIdx.x;
    const int w  = blockIdx.x;
    const int bh = blockIdx.y;
    const float* Qp = g_qkv + ((long long)bh * NNN + w * WINW) * DHH;
    const float* Kp = g_qkv + (((long long)BB * HHH + bh) * NNN + w * WINW) * DHH;
    const float* Vp = g_qkv + (((long long)2 * BB * HHH + bh) * NNN + w * WINW) * DHH;

    #pragma unroll
    for (int r = 0; r < 4; r++) {
        int idx = t + r * 128;
        int i = idx >> 5, d = idx & 31;
        ql[i * 33 + d] = Qp[idx];
        kl[i * 33 + d] = Kp[idx];
        vl[i * 33 + d] = Vp[idx];
    }
    __syncthreads();
    #pragma unroll
    for (int r = 0; r < 2; r++) {
        int p = t + r * 128;
        int i = p >> 4, j = p & 15;
        float a = 0.f;
        #pragma unroll
        for (int d = 0; d < 32; d++) a += ql[i * 33 + d] * kl[j * 33 + d];
        sl[i * 17 + j] = a * SCALE;
    }
    __syncthreads();
    if (t < 16) {
        float m = -1e30f;
        #pragma unroll
        for (int j = 0; j < 16; j++) m = fmaxf(m, sl[t * 17 + j]);
        float s = 0.f;
        #pragma unroll
        for (int j = 0; j < 16; j++) { float e = __expf(sl[t * 17 + j] - m); sl[t * 17 + j] = e; s += e; }
        float inv = 1.0f / s;
        #pragma unroll
        for (int j = 0; j < 16; j++) sl[t * 17 + j] *= inv;
    }
    __syncthreads();
    const int b = bh >> 3, h = bh & 7;
    float* cb = g_comb + ((long long)b * NNN + w * WINW) * CCC + h * DHH;
    #pragma unroll
    for (int r = 0; r < 4; r++) {
        int p = t + r * 128;
        int i = p >> 5, d = p & 31;
        float a = 0.f;
        #pragma unroll
        for (int j = 0; j < 16; j++) a += sl[i * 17 + j] * vl[j * 33 + d];
        cb[(long long)i * CCC + d] += a;
    }
}

// ============================================================
// Kernel 4: output projection.  g_comb[8192,256] @ Wp[256,256] + b -> out
// ============================================================
__global__ __launch_bounds__(256) void proj_gemm_kernel(const float* __restrict__ W,
                                                        const float* __restrict__ bias,
                                                        float* __restrict__ out) {
    __shared__ float Xs[16 * 68];
    __shared__ float Ws[16 * 64];
    const int t  = threadIdx.x;
    const int tx = t & 15, ty = t >> 4;
    const int m0 = blockIdx.y * 64;
    const int n0 = blockIdx.x * 64;

    float acc[4][4] = {};
    for (int k0 = 0; k0 < CCC; k0 += 16) {
        {
            int kk = t & 15, mloc = t >> 4;
            #pragma unroll
            for (int r = 0; r < 4; r++) {
                int m = mloc + r * 16;
                Xs[kk * 68 + m] = g_comb[(long long)(m0 + m) * CCC + k0 + kk];
            }
        }
        {
            int nn = t & 63, kk = t >> 6;
            #pragma unroll
            for (int r = 0; r < 4; r++)
                Ws[(kk + r * 4) * 64 + nn] = W[(long long)(k0 + kk + r * 4) * CCC + n0 + nn];
        }
        __syncthreads();
        #pragma unroll
        for (int kk = 0; kk < 16; kk++) {
            float4 a = *(const float4*)(Xs + kk * 68 + ty * 4);
            float4 b = *(const float4*)(Ws + kk * 64 + tx * 4);
            acc[0][0] += a.x * b.x; acc[0][1] += a.x * b.y; acc[0][2] += a.x * b.z; acc[0][3] += a.x * b.w;
            acc[1][0] += a.y * b.x; acc[1][1] += a.y * b.y; acc[1][2] += a.y * b.z; acc[1][3] += a.y * b.w;
            acc[2][0] += a.z * b.x; acc[2][1] += a.z * b.y; acc[2][2] += a.z * b.z; acc[2][3] += a.z * b.w;
            acc[3][0] += a.w * b.x; acc[3][1] += a.w * b.y; acc[3][2] += a.w * b.z; acc[3][3] += a.w * b.w;
        }
        __syncthreads();
    }
    #pragma unroll
    for (int ii = 0; ii < 4; ii++) {
        int row = m0 + ty * 4 + ii;
        #pragma unroll
        for (int jj = 0; jj < 4; jj++) {
            int col = n0 + tx * 4 + jj;
            out[(long long)row * CCC + col] = acc[ii][jj] + bias[col];
        }
    }
}

// ============================================================
extern "C" void kernel_launch(void* const* d_in, const int* in_sizes, int n_in,
                              void* d_out, int out_size) {
    const float* x     = (const float*)d_in[0];
    const float* Wqkv  = (const float*)d_in[1];
    const float* Wproj = (const float*)d_in[2];
    const float* bproj = (const float*)d_in[3];
    float* out   = (float*)d_out;
    float* out_w = out + (long long)BB * NNN * CCC;

    cudaFuncSetAttribute(attn_global_kernel,
                         cudaFuncAttributeMaxDynamicSharedMemorySize, ATTN_SMEM);

    qkv_gemm_kernel<<<dim3(12, 128), 256>>>(x, Wqkv);
    attn_global_kernel<<<dim3(NNN / 16, BB * HHH), 256, ATTN_SMEM>>>(out_w);
    local_attn_kernel<<<dim3(NNN / WINW, BB * HHH), 128>>>();
    proj_gemm_kernel<<<dim3(CCC / 64, (BB * NNN) / 64), 256>>>(Wproj, bproj, out);
}